// round 9
// baseline (speedup 1.0000x reference)
#include <cuda_runtime.h>
#include <cstdint>

// Problem constants
#define GM 9600          // B*Lq = 32*300
#define GK 256           // D_MODEL
#define NRAW 288         // 192 offset cols + 96 attn cols
#define BM 64
#define BN 96
#define BK 32

// Scratch for raw GEMM output (query @ [W_off | W_attn] + bias), ~11 MB.
__device__ float g_raw[GM * NRAW];

// ---- packed dual-fp32 FMA (sm_103a). One instr = 2 IEEE fp32 FMAs. ----
__device__ __forceinline__ unsigned long long fma_f32x2(
    unsigned long long a, unsigned long long b, unsigned long long c) {
    unsigned long long d;
    asm("fma.rn.f32x2 %0, %1, %2, %3;" : "=l"(d) : "l"(a), "l"(b), "l"(c));
    return d;
}
__device__ __forceinline__ unsigned long long pack2dup(float x) {
    unsigned long long r;
    asm("mov.b64 %0, {%1, %2};" : "=l"(r) : "f"(x), "f"(x));
    return r;
}
__device__ __forceinline__ void unpack2(unsigned long long p, float& lo, float& hi) {
    asm("mov.b64 {%0, %1}, %2;" : "=f"(lo), "=f"(hi) : "l"(p));
}

// ---------------------------------------------------------------------------
// Kernel 1: fused GEMM  raw[9600][288] = query @ [W_off(192) | W_attn(96)] + b
// Double-buffered SMEM fp32 GEMM using packed f32x2 FMAs.
// grid = (150, 3): y=0,1 -> W_off halves, y=2 -> W_attn.
// 256 threads as 16(m) x 16(n), micro-tile 4m x 6n (= 4x3 packed pairs).
// ---------------------------------------------------------------------------
__global__ __launch_bounds__(256) void dfine_gemm_kernel(
    const float* __restrict__ A,      // query (9600 x 256)
    const float* __restrict__ Woff,   // (256 x 192)
    const float* __restrict__ boff,   // (192)
    const float* __restrict__ Wattn,  // (256 x 96)
    const float* __restrict__ battn)  // (96)
{
    __shared__ float As[2][BK][68];   // padded: 16B-aligned float4 rows, no STS conflict
    __shared__ float Bs[2][BK][BN];

    const int tid  = threadIdx.x;
    const int rowBase = blockIdx.x * BM;
    const int nblk = blockIdx.y;

    const float* Bsrc;
    const float* bias;
    int ldB, colBase, nGlobalBase;
    if (nblk < 2) { Bsrc = Woff;  bias = boff;  ldB = 192; colBase = nblk * 96; nGlobalBase = nblk * 96; }
    else          { Bsrc = Wattn; bias = battn; ldB = 96;  colBase = 0;         nGlobalBase = 192; }

    const int ty = tid >> 4;   // 0..15 (m)
    const int tx = tid & 15;   // 0..15 (n)

    // A-load mapping (2 float4 per thread)
    const int fA0 = tid;
    const int rA0 = fA0 >> 3, kqA0 = fA0 & 7;
    const int fA1 = tid + 256;
    const int rA1 = fA1 >> 3, kqA1 = fA1 & 7;

    unsigned long long acc2[4][3];    // [m][n-pair], each = 2 fp32 accumulators
    #pragma unroll
    for (int i = 0; i < 4; i++)
        #pragma unroll
        for (int j = 0; j < 3; j++) acc2[i][j] = 0ull;

    float4 avr[2];
    float  bvr[12];

    // ---- prologue: load tile 0 into regs, store to buf 0
    {
        avr[0] = *reinterpret_cast<const float4*>(A + (rowBase + rA0) * GK + kqA0 * 4);
        avr[1] = *reinterpret_cast<const float4*>(A + (rowBase + rA1) * GK + kqA1 * 4);
        #pragma unroll
        for (int i = 0; i < 12; i++) {
            int e = tid + i * 256;
            int k = e / 96;
            int n = e - k * 96;
            bvr[i] = __ldg(Bsrc + k * ldB + colBase + n);
        }
        As[0][kqA0 * 4 + 0][rA0] = avr[0].x;
        As[0][kqA0 * 4 + 1][rA0] = avr[0].y;
        As[0][kqA0 * 4 + 2][rA0] = avr[0].z;
        As[0][kqA0 * 4 + 3][rA0] = avr[0].w;
        As[0][kqA1 * 4 + 0][rA1] = avr[1].x;
        As[0][kqA1 * 4 + 1][rA1] = avr[1].y;
        As[0][kqA1 * 4 + 2][rA1] = avr[1].z;
        As[0][kqA1 * 4 + 3][rA1] = avr[1].w;
        #pragma unroll
        for (int i = 0; i < 12; i++) {
            int e = tid + i * 256;
            int k = e / 96;
            int n = e - k * 96;
            Bs[0][k][n] = bvr[i];
        }
    }
    __syncthreads();

    const int NT = GK / BK;   // 8 tiles
    for (int t = 0; t < NT; t++) {
        const int cur = t & 1;
        if (t + 1 < NT) {
            const int k0 = (t + 1) * BK;
            avr[0] = *reinterpret_cast<const float4*>(A + (rowBase + rA0) * GK + k0 + kqA0 * 4);
            avr[1] = *reinterpret_cast<const float4*>(A + (rowBase + rA1) * GK + k0 + kqA1 * 4);
            #pragma unroll
            for (int i = 0; i < 12; i++) {
                int e = tid + i * 256;
                int k = e / 96;
                int n = e - k * 96;
                bvr[i] = __ldg(Bsrc + (k0 + k) * ldB + colBase + n);
            }
        }

        // compute on current buffer: per k, 4 dup-packs + 3 packed-B LDS.64
        // + 12 fma.rn.f32x2 (= 24 fp32 FMAs)
        #pragma unroll
        for (int k = 0; k < BK; k++) {
            float4 av = *reinterpret_cast<const float4*>(&As[cur][k][ty * 4]);
            unsigned long long a2[4];
            a2[0] = pack2dup(av.x);
            a2[1] = pack2dup(av.y);
            a2[2] = pack2dup(av.z);
            a2[3] = pack2dup(av.w);
            unsigned long long b2[3];
            b2[0] = *reinterpret_cast<const unsigned long long*>(&Bs[cur][k][tx * 6 + 0]);
            b2[1] = *reinterpret_cast<const unsigned long long*>(&Bs[cur][k][tx * 6 + 2]);
            b2[2] = *reinterpret_cast<const unsigned long long*>(&Bs[cur][k][tx * 6 + 4]);
            #pragma unroll
            for (int i = 0; i < 4; i++)
                #pragma unroll
                for (int j = 0; j < 3; j++)
                    acc2[i][j] = fma_f32x2(a2[i], b2[j], acc2[i][j]);
        }

        if (t + 1 < NT) {
            const int nxt = 1 - cur;
            As[nxt][kqA0 * 4 + 0][rA0] = avr[0].x;
            As[nxt][kqA0 * 4 + 1][rA0] = avr[0].y;
            As[nxt][kqA0 * 4 + 2][rA0] = avr[0].z;
            As[nxt][kqA0 * 4 + 3][rA0] = avr[0].w;
            As[nxt][kqA1 * 4 + 0][rA1] = avr[1].x;
            As[nxt][kqA1 * 4 + 1][rA1] = avr[1].y;
            As[nxt][kqA1 * 4 + 2][rA1] = avr[1].z;
            As[nxt][kqA1 * 4 + 3][rA1] = avr[1].w;
            #pragma unroll
            for (int i = 0; i < 12; i++) {
                int e = tid + i * 256;
                int k = e / 96;
                int n = e - k * 96;
                Bs[nxt][k][n] = bvr[i];
            }
        }
        __syncthreads();
    }

    // ---- epilogue: unpack, add bias, write to g_raw
    #pragma unroll
    for (int i = 0; i < 4; i++) {
        int r = rowBase + ty * 4 + i;
        #pragma unroll
        for (int j = 0; j < 3; j++) {
            float lo, hi;
            unpack2(acc2[i][j], lo, hi);
            int n = tx * 6 + 2 * j;
            g_raw[r * NRAW + nGlobalBase + n + 0] = lo + __ldg(bias + colBase + n + 0);
            g_raw[r * NRAW + nGlobalBase + n + 1] = hi + __ldg(bias + colBase + n + 1);
        }
    }
}

// ---------------------------------------------------------------------------
// Kernel 2: fused softmax + location transform + bilinear gather + weighted sum
// Block = 256 threads = 4 queries x 64 threads; each thread = 4 channels
// (float4). Corner indices are CLAMPED (never invalid) and OOB corners get
// weight 0, so the gather loop is 48 unconditional LDG.128 + FFMA with no
// branches -> maximal memory-level parallelism. Two accumulator chains.
// ---------------------------------------------------------------------------
__global__ __launch_bounds__(256) void dfine_sample_kernel(
    const float* __restrict__ refp,   // (32,300,1,4)
    const float* __restrict__ value,  // input_flatten (32, 8400, 256)
    float* __restrict__ out)          // (32,300,256)
{
    __shared__ int   sOffs[4][96][4];  // clamped absolute spatial index (0..8399)
    __shared__ float sWts[4][96][4];   // bilinear weights * softmax weight (0 if OOB)
    __shared__ float sLog[4][96];      // attn logits -> probabilities

    const int tid  = threadIdx.x;
    const int row0 = blockIdx.x * 4;   // 300 % 4 == 0 -> never straddles a batch

    // ---- Phase A: per-(query,head,point) address/weight precompute
    #pragma unroll
    for (int e = tid; e < 384; e += 256) {
        int qi = e / 96, j = e % 96;       // j = h*12 + pt
        int row = row0 + qi;
        const float* raw = g_raw + (size_t)row * NRAW;
        float rx = __ldg(refp + row * 4 + 0);
        float ry = __ldg(refp + row * 4 + 1);
        float rw = __ldg(refp + row * 4 + 2);
        float rh = __ldg(refp + row * 4 + 3);
        float ox = raw[2 * j + 0];
        float oy = raw[2 * j + 1];
        sLog[qi][j] = raw[192 + j];

        int pt  = j % 12;
        int lvl = pt >> 2;
        int   W    = (lvl == 0) ? 80 : (lvl == 1) ? 40 : 20;  // H == W
        int   loff = (lvl == 0) ? 0  : (lvl == 1) ? 6400 : 8000;
        float Wf   = (float)W;
        // pscale=1/4, OFFSET_SCALE=0.5 -> 0.125; pixel = loc*W - 0.5
        float ix = (rx + ox * 0.125f * rw) * Wf - 0.5f;
        float iy = (ry + oy * 0.125f * rh) * Wf - 0.5f;
        float fx0 = floorf(ix), fy0 = floorf(iy);
        float fx = ix - fx0, fy = iy - fy0;
        int x0 = (int)fx0, y0 = (int)fy0;
        int x1 = x0 + 1,   y1 = y0 + 1;
        bool vx0 = (unsigned)x0 < (unsigned)W;
        bool vx1 = (unsigned)x1 < (unsigned)W;
        bool vy0 = (unsigned)y0 < (unsigned)W;
        bool vy1 = (unsigned)y1 < (unsigned)W;
        int cx0 = min(max(x0, 0), W - 1), cx1 = min(max(x1, 0), W - 1);
        int cy0 = min(max(y0, 0), W - 1), cy1 = min(max(y1, 0), W - 1);
        sOffs[qi][j][0] = loff + cy0 * W + cx0;
        sOffs[qi][j][1] = loff + cy0 * W + cx1;
        sOffs[qi][j][2] = loff + cy1 * W + cx0;
        sOffs[qi][j][3] = loff + cy1 * W + cx1;
        float gx = 1.0f - fx, gy = 1.0f - fy;
        sWts[qi][j][0] = (vx0 && vy0) ? gx * gy : 0.0f;
        sWts[qi][j][1] = (vx1 && vy0) ? fx * gy : 0.0f;
        sWts[qi][j][2] = (vx0 && vy1) ? gx * fy : 0.0f;
        sWts[qi][j][3] = (vx1 && vy1) ? fx * fy : 0.0f;
    }
    __syncthreads();

    // ---- Phase B: per-(query,head) softmax over 12 points (in place)
    if (tid < 32) {
        int qi = tid >> 3, h = tid & 7;
        float* L = &sLog[qi][h * 12];
        float m = -1e30f;
        #pragma unroll
        for (int p = 0; p < 12; p++) m = fmaxf(m, L[p]);
        float s = 0.0f;
        #pragma unroll
        for (int p = 0; p < 12; p++) { float ev = expf(L[p] - m); L[p] = ev; s += ev; }
        float inv = 1.0f / s;
        #pragma unroll
        for (int p = 0; p < 12; p++) L[p] *= inv;
    }
    __syncthreads();

    // ---- Phase C: fold softmax weight into bilinear weights
    #pragma unroll
    for (int e = tid; e < 384; e += 256) {
        int qi = e / 96, j = e % 96;
        float w = sLog[qi][j];
        sWts[qi][j][0] *= w;
        sWts[qi][j][1] *= w;
        sWts[qi][j][2] *= w;
        sWts[qi][j][3] *= w;
    }
    __syncthreads();

    // ---- Phase D: branch-free gather + accumulate
    const int qi   = tid >> 6;         // query within block
    const int lane = tid & 63;         // channel-quad index 0..63
    const int h    = lane >> 3;        // head (8 channel-quads per head)
    const int row  = row0 + qi;
    const int b    = row / 300;

    const float4* __restrict__ vb =
        (const float4*)value + (size_t)b * 8400 * 64 + h * 8 + (lane & 7);

    float4 accA = make_float4(0.0f, 0.0f, 0.0f, 0.0f);
    float4 accB = make_float4(0.0f, 0.0f, 0.0f, 0.0f);
    #pragma unroll
    for (int pp = 0; pp < 6; pp++) {
        // two points per iteration -> two independent accumulator chains
        {
            int j = h * 12 + 2 * pp;
            int4   o = *reinterpret_cast<const int4*>(sOffs[qi][j]);
            float4 w = *reinterpret_cast<const float4*>(sWts[qi][j]);
            float4 v0 = __ldg(vb + (size_t)o.x * 64);
            float4 v1 = __ldg(vb + (size_t)o.y * 64);
            float4 v2 = __ldg(vb + (size_t)o.z * 64);
            float4 v3 = __ldg(vb + (size_t)o.w * 64);
            accA.x += w.x * v0.x; accA.y += w.x * v0.y; accA.z += w.x * v0.z; accA.w += w.x * v0.w;
            accA.x += w.y * v1.x; accA.y += w.y * v1.y; accA.z += w.y * v1.z; accA.w += w.y * v1.w;
            accA.x += w.z * v2.x; accA.y += w.z * v2.y; accA.z += w.z * v2.z; accA.w += w.z * v2.w;
            accA.x += w.w * v3.x; accA.y += w.w * v3.y; accA.z += w.w * v3.z; accA.w += w.w * v3.w;
        }
        {
            int j = h * 12 + 2 * pp + 1;
            int4   o = *reinterpret_cast<const int4*>(sOffs[qi][j]);
            float4 w = *reinterpret_cast<const float4*>(sWts[qi][j]);
            float4 v0 = __ldg(vb + (size_t)o.x * 64);
            float4 v1 = __ldg(vb + (size_t)o.y * 64);
            float4 v2 = __ldg(vb + (size_t)o.z * 64);
            float4 v3 = __ldg(vb + (size_t)o.w * 64);
            accB.x += w.x * v0.x; accB.y += w.x * v0.y; accB.z += w.x * v0.z; accB.w += w.x * v0.w;
            accB.x += w.y * v1.x; accB.y += w.y * v1.y; accB.z += w.y * v1.z; accB.w += w.y * v1.w;
            accB.x += w.z * v2.x; accB.y += w.z * v2.y; accB.z += w.z * v2.z; accB.w += w.z * v2.w;
            accB.x += w.w * v3.x; accB.y += w.w * v3.y; accB.z += w.w * v3.z; accB.w += w.w * v3.w;
        }
    }

    float4 acc = make_float4(accA.x + accB.x, accA.y + accB.y,
                             accA.z + accB.z, accA.w + accB.w);
    reinterpret_cast<float4*>(out)[(size_t)row * 64 + lane] = acc;
}

// ---------------------------------------------------------------------------
// Launch: inputs in metadata order:
//   0 query (32,300,256) f32        1 reference_points (32,300,1,4) f32
//   2 input_flatten (32,8400,256)   3 W_off (256,192)   4 b_off (192)
//   5 W_attn (256,96)               6 b_attn (96)
// Output: (32,300,256) f32
// ---------------------------------------------------------------------------
extern "C" void kernel_launch(void* const* d_in, const int* in_sizes, int n_in,
                              void* d_out, int out_size) {
    const float* query = (const float*)d_in[0];
    const float* refp  = (const float*)d_in[1];
    const float* value = (const float*)d_in[2];
    const float* Woff  = (const float*)d_in[3];
    const float* boff  = (const float*)d_in[4];
    const float* Wattn = (const float*)d_in[5];
    const float* battn = (const float*)d_in[6];
    float* out = (float*)d_out;

    dim3 ggrid(GM / BM, 3);  // 150 x 3
    dfine_gemm_kernel<<<ggrid, 256>>>(query, Woff, boff, Wattn, battn);
    dfine_sample_kernel<<<GM / 4, 256>>>(refp, value, out);
}